// round 9
// baseline (speedup 1.0000x reference)
#include <cuda_runtime.h>
#include <math.h>
#include <stdint.h>

#define DIM     512
#define NQ      64
#define NB      2048
#define NM      131328          /* 512*513/2 */
#define ESLICES 4
#define EC      128             /* e per CTA */
#define BTILE   64
#define NCHUNK  (EC * 4)        /* 512 chunks per CTA, 32 KB each */
#define PRE_BLOCKS 1024

typedef unsigned long long ull;

/* W layout: [e][d/2][k][2]  (f32x2 lane = d parity) */
#define W2OFF(e, d, k) (((size_t)(e) << 15) + (size_t)((((d) >> 1) << 7) + ((k) << 1) + ((d) & 1)))

/* ---- scratch (static device globals; no allocation APIs) ---- */
__device__ float g_W[(size_t)DIM * DIM * NQ];              /* 64 MB */
__device__ float g_grad_part[(size_t)ESLICES * NB * NQ];
__device__ float g_pg_part  [(size_t)ESLICES * NB * NQ];
__device__ float g_nsq_part [(size_t)PRE_BLOCKS * NQ];
__device__ float g_norm[NQ];

/* ---- f32x2 helpers ---- */
__device__ __forceinline__ void fma2(ull& d, ull a, ull b) {   /* d = a*b + d */
    asm("fma.rn.f32x2 %0, %1, %2, %0;" : "+l"(d) : "l"(a), "l"(b));
}
__device__ __forceinline__ float2 up2(ull v) {
    float2 r; asm("mov.b64 {%0, %1}, %2;" : "=f"(r.x), "=f"(r.y) : "l"(v)); return r;
}

/* ============================================================
 * Kernel 1: build scaled symmetric W (d-pair-lane layout) + norms
 * ============================================================ */
__global__ __launch_bounds__(256) void hsq_prep_kernel(const float* __restrict__ q_coefs)
{
    const int t  = threadIdx.x;
    const int k  = t & 63;
    const int ms = t >> 6;
    float nsq = 0.0f;

    for (int base = blockIdx.x * 4; base < NM; base += gridDim.x * 4) {
        const int m = base + ms;
        if (m < NM) {
            const float q = q_coefs[(size_t)m * NQ + k];
            int i = (int)((2.0f * DIM + 1.0f -
                           sqrtf((float)(2 * DIM + 1) * (2 * DIM + 1) - 8.0f * (float)m)) * 0.5f);
            if (i < 0) i = 0;
            if (i > DIM - 1) i = DIM - 1;
            while (i > 0 && (i * DIM - (i * (i - 1)) / 2) > m) i--;
            while (i < DIM - 1 && ((i + 1) * DIM - ((i + 1) * i) / 2) <= m) i++;
            const int j = i + (m - (i * DIM - (i * (i - 1)) / 2));

            const float v = q * ((i == j) ? 2.0f : 1.4142135623730951f);
            g_W[W2OFF(i, j, k)] = v;
            if (i != j)
                g_W[W2OFF(j, i, k)] = v;
            nsq += q * q;
        }
    }

    __shared__ float red[256];
    red[t] = nsq;
    __syncthreads();
    if (ms == 0)
        g_nsq_part[(size_t)blockIdx.x * NQ + k] =
            red[k] + red[64 + k] + red[128 + k] + red[192 + k];
}

/* ============================================================
 * Kernel 2: finalize norms (fixed order)
 * ============================================================ */
__global__ void hsq_norm_kernel()
{
    const int k = threadIdx.x;
    float s = 0.0f;
    for (int b = 0; b < PRE_BLOCKS; b++)
        s += g_nsq_part[(size_t)b * NQ + k];
    g_norm[k] = sqrtf(s);
}

/* ============================================================
 * Kernel 3: main contraction.
 * 512 threads: warp kg=0..15 owns k 4kg..4kg+3, lane bg owns b rows
 * 2bg, 2bg+1. f32x2 lanes carry (even-d, odd-d) partials:
 * all operands pack-free, all LDS conflict-free / broadcast.
 * ============================================================ */
__global__ __launch_bounds__(512, 1) void hsq_main_kernel(const float* __restrict__ points,
                                                          const float* __restrict__ l_coefs)
{
    extern __shared__ float smem[];
    float* psp = smem;              /* [256 dpair][64 b][2] = 32768 fl (128 KB) */
    float* wsm = smem + 32768;      /* 2 x [64 dpair][64 k][2] = 2 x 8192 fl   */

    const int bt = blockIdx.x;
    const int es = blockIdx.y;
    const int b0 = bt * BTILE;
    const int e0 = es * EC;
    const int t  = threadIdx.x;
    const int kg = t >> 5;          /* warp id: k block */
    const int bg = t & 31;          /* lane: b-pair     */

    const uint32_t wsa = (uint32_t)__cvta_generic_to_shared(wsm);

    /* prefetch W chunk 0 (32 KB contiguous) */
    {
        const float* src = g_W + ((size_t)e0 << 15);
        #pragma unroll
        for (int i = 0; i < 4; i++)
            asm volatile("cp.async.cg.shared.global [%0], [%1], 16;"
                         :: "r"(wsa + (uint32_t)((t + i * 512) * 16)),
                            "l"(src + (t + i * 512) * 4));
        asm volatile("cp.async.commit_group;");
    }

    /* stage P transposed + d-pair-packed: psp[(d>>1)*128 + b*2 + (d&1)] */
    for (int idx = t; idx < BTILE * DIM; idx += 512) {
        const int b = idx >> 9;
        const int d = idx & 511;
        psp[((d >> 1) << 7) + (b << 1) + (d & 1)] = points[(size_t)(b0 + b) * DIM + d];
    }

    float grad[2][4] = {};
    float pg[2][4]   = {};

    int ci = 0;
    for (int ee = 0; ee < EC; ee++) {
        ull acc[2][4] = {};

        for (int dc = 0; dc < 4; dc++, ci++) {
            if (ci + 1 < NCHUNK) {
                const int nci = ci + 1;
                /* 8192 floats (32 KB) per chunk within an e-block: offset (nci&3)<<13 */
                const float* src = g_W + ((size_t)(e0 + (nci >> 2)) << 15) + ((size_t)(nci & 3) << 13);
                const uint32_t dst = wsa + (uint32_t)((nci & 1) * 32768);
                #pragma unroll
                for (int i = 0; i < 4; i++)
                    asm volatile("cp.async.cg.shared.global [%0], [%1], 16;"
                                 :: "r"(dst + (uint32_t)((t + i * 512) * 16)),
                                    "l"(src + (t + i * 512) * 4));
            }
            asm volatile("cp.async.commit_group;");
            asm volatile("cp.async.wait_group 1;");
            __syncthreads();

            const float* wt = wsm + (ci & 1) * 8192 + kg * 8;
            const float* pt = psp + dc * 8192 + bg * 4;

            #pragma unroll 4
            for (int dp = 0; dp < 64; dp++) {
                const ulonglong2 w0 = *(const ulonglong2*)(wt + dp * 128);      /* k0,k1 d-pairs */
                const ulonglong2 w1 = *(const ulonglong2*)(wt + dp * 128 + 4);  /* k2,k3 d-pairs */
                const ulonglong2 pv = *(const ulonglong2*)(pt + dp * 128);      /* b0,b1 d-pairs */
                fma2(acc[0][0], pv.x, w0.x);
                fma2(acc[0][1], pv.x, w0.y);
                fma2(acc[0][2], pv.x, w1.x);
                fma2(acc[0][3], pv.x, w1.y);
                fma2(acc[1][0], pv.y, w0.x);
                fma2(acc[1][1], pv.y, w0.y);
                fma2(acc[1][2], pv.y, w1.x);
                fma2(acc[1][3], pv.y, w1.y);
            }
            __syncthreads();
        }

        /* e-fold: g = lane0+lane1+l ; grad += g^2 ; pg += p_e * g */
        const int e = e0 + ee;
        const ulonglong2 lvu = *(const ulonglong2*)(l_coefs + (size_t)e * NQ + kg * 4);
        const float2 l01 = up2(lvu.x);
        const float2 l23 = up2(lvu.y);
        const float lk[4] = { l01.x, l01.y, l23.x, l23.y };

        #pragma unroll
        for (int i = 0; i < 2; i++) {
            const float pe = psp[((e >> 1) << 7) + ((bg * 2 + i) << 1) + (e & 1)];
            #pragma unroll
            for (int j = 0; j < 4; j++) {
                const float2 a = up2(acc[i][j]);
                const float g = (a.x + a.y) + lk[j];
                grad[i][j] = fmaf(g, g, grad[i][j]);
                pg[i][j]   = fmaf(pe, g, pg[i][j]);
            }
        }
    }

    #pragma unroll
    for (int i = 0; i < 2; i++) {
        const size_t o = ((size_t)es * NB + (b0 + bg * 2 + i)) * NQ + kg * 4;
        *(float4*)(g_grad_part + o) = make_float4(grad[i][0], grad[i][1], grad[i][2], grad[i][3]);
        *(float4*)(g_pg_part   + o) = make_float4(pg[i][0],   pg[i][1],   pg[i][2],   pg[i][3]);
    }
}

/* ============================================================
 * Kernel 4: epilogue — sum partials, p.l dot, score formula
 * ============================================================ */
__global__ __launch_bounds__(256) void hsq_score_kernel(const float* __restrict__ points,
                                                        const float* __restrict__ l_coefs,
                                                        const float* __restrict__ free_coefs,
                                                        float* __restrict__ out)
{
    __shared__ float psh[4 * DIM];
    const int b0 = blockIdx.x * 4;
    const int t  = threadIdx.x;

    for (int idx = t; idx < 4 * DIM; idx += 256)
        psh[idx] = points[(size_t)b0 * DIM + idx];
    __syncthreads();

    const int k  = t & 63;
    const int bi = t >> 6;
    const int b  = b0 + bi;
    const float* pr = psh + bi * DIM;

    float pl = 0.0f;
    #pragma unroll 8
    for (int d = 0; d < DIM; d++)
        pl = fmaf(pr[d], l_coefs[(size_t)d * NQ + k], pl);

    float grad = 0.0f, pg = 0.0f;
    #pragma unroll
    for (int s = 0; s < ESLICES; s++) {
        const size_t o = ((size_t)s * NB + b) * NQ + k;
        grad += g_grad_part[o];
        pg   += g_pg_part[o];
    }

    const float nrm    = g_norm[k];
    /* values = |q@coefs + p.l + free| = |(p.g + p.l)/2 + free| */
    const float values = fabsf(0.5f * (pg + pl) + free_coefs[k]);
    const float score  = (sqrtf(grad * 0.25f + values * nrm) - 0.5f * sqrtf(grad)) / nrm;
    out[(size_t)b * NQ + k] = score;
}

/* ============================================================ */
extern "C" void kernel_launch(void* const* d_in, const int* in_sizes, int n_in,
                              void* d_out, int out_size)
{
    const float* points = nullptr;
    const float* q      = nullptr;
    const float* l      = nullptr;
    const float* fr     = nullptr;

    for (int i = 0; i < n_in; i++) {
        switch (in_sizes[i]) {
            case NB * DIM:  points = (const float*)d_in[i]; break;
            case NM * NQ:   q      = (const float*)d_in[i]; break;
            case DIM * NQ:  l      = (const float*)d_in[i]; break;
            case NQ:        fr     = (const float*)d_in[i]; break;
        }
    }
    if (!points) points = (const float*)d_in[0];
    if (!q)      q      = (const float*)d_in[1];
    if (!l)      l      = (const float*)d_in[2];
    if (!fr)     fr     = (const float*)d_in[3];

    const int smem = (32768 + 2 * 8192) * 4; /* 196608 B */
    cudaFuncSetAttribute(hsq_main_kernel, cudaFuncAttributeMaxDynamicSharedMemorySize, smem);

    hsq_prep_kernel<<<PRE_BLOCKS, 256>>>(q);
    hsq_norm_kernel<<<1, 64>>>();

    dim3 grid(NB / BTILE, ESLICES); /* (32, 4) — single wave */
    hsq_main_kernel<<<grid, 512, smem>>>(points, l);

    hsq_score_kernel<<<NB / 4, 256>>>(points, l, fr, (float*)d_out);
}

// round 11
// speedup vs baseline: 2.4968x; 2.4968x over previous
#include <cuda_runtime.h>
#include <cuda_bf16.h>
#include <math.h>
#include <stdint.h>

#define DIM   512
#define NQ    64
#define NB    2048
#define NTOT  32768                 /* N = 512 e * 64 k */
#define SQRT2 1.4142135623730951f

/* ---- scratch (static device globals; no allocation APIs) ---- */
__device__ __nv_bfloat16 g_Wh[(size_t)NTOT * DIM];   /* W hi, [n=(e,k)][d], 32 MB */
__device__ __nv_bfloat16 g_Wl[(size_t)NTOT * DIM];   /* W lo */
__device__ __nv_bfloat16 g_Ph[(size_t)NB * DIM];     /* P hi */
__device__ __nv_bfloat16 g_Pl[(size_t)NB * DIM];     /* P lo */
__device__ float         g_G [(size_t)DIM * NB * NQ];/* G[e][b][k] fp32, 256 MB */
__device__ float         g_nsq_part[DIM * NQ];
__device__ float         g_norm[NQ];

#define SWZ(o) ((o) ^ (((o) >> 3) & 0x70))

__device__ __forceinline__ void cpa16(uint32_t dst, const void* src) {
    asm volatile("cp.async.cg.shared.global [%0], [%1], 16;" :: "r"(dst), "l"(src));
}
__device__ __forceinline__ uint32_t s2u(const void* p) {
    return (uint32_t)__cvta_generic_to_shared(p);
}
__device__ __forceinline__ void ldsm4(uint32_t* r, uint32_t addr) {
    asm volatile("ldmatrix.sync.aligned.m8n8.x4.shared.b16 {%0,%1,%2,%3}, [%4];"
                 : "=r"(r[0]), "=r"(r[1]), "=r"(r[2]), "=r"(r[3]) : "r"(addr));
}
__device__ __forceinline__ void mma16816(float* c, const uint32_t* a, const uint32_t* b) {
    asm volatile(
        "mma.sync.aligned.m16n8k16.row.col.f32.bf16.bf16.f32 "
        "{%0,%1,%2,%3}, {%4,%5,%6,%7}, {%8,%9}, {%0,%1,%2,%3};"
        : "+f"(c[0]), "+f"(c[1]), "+f"(c[2]), "+f"(c[3])
        : "r"(a[0]), "r"(a[1]), "r"(a[2]), "r"(a[3]), "r"(b[0]), "r"(b[1]));
}

/* ============================================================
 * Kernel 0: split P into bf16 hi/lo
 * ============================================================ */
__global__ __launch_bounds__(256) void hsq_psplit(const float* __restrict__ points)
{
    for (int i = blockIdx.x * 256 + threadIdx.x; i < NB * DIM; i += gridDim.x * 256) {
        const float v = points[i];
        const __nv_bfloat16 h = __float2bfloat16(v);
        g_Ph[i] = h;
        g_Pl[i] = __float2bfloat16(v - __bfloat162float(h));
    }
}

/* ============================================================
 * Kernel 1: build W-bf16 [n=(e,k)][d] hi/lo (gather + smem
 * transpose) + partial column norms of raw q_coefs. 1 block/e.
 * ============================================================ */
__global__ __launch_bounds__(256) void hsq_prep(const float* __restrict__ q_coefs)
{
    __shared__ float vs[64][65];
    const int e  = blockIdx.x;
    const int t  = threadIdx.x;
    const int k  = t & 63;
    const int ds = t >> 6;
    float nsq = 0.0f;

    for (int d0 = 0; d0 < DIM; d0 += 64) {
        #pragma unroll 4
        for (int it = 0; it < 16; it++) {
            const int d = d0 + it * 4 + ds;
            const int i = d < e ? d : e;
            const int j = d < e ? e : d;
            const int m = i * DIM - (i * (i - 1)) / 2 + (j - i);
            const float qv = q_coefs[(size_t)m * NQ + k];
            vs[it * 4 + ds][k] = qv * ((d == e) ? 2.0f : SQRT2);
            if (d <= e) nsq += qv * qv;
        }
        __syncthreads();
        const int dl = t & 63;
        const int ks = t >> 6;
        #pragma unroll 4
        for (int kk = 0; kk < 16; kk++) {
            const int kq = kk * 4 + ks;
            const float v = vs[dl][kq];
            const __nv_bfloat16 h = __float2bfloat16(v);
            const size_t o = ((size_t)((e << 6) + kq)) * DIM + d0 + dl;
            g_Wh[o] = h;
            g_Wl[o] = __float2bfloat16(v - __bfloat162float(h));
        }
        __syncthreads();
    }

    __shared__ float red[256];
    red[t] = nsq;
    __syncthreads();
    if (ds == 0)
        g_nsq_part[e * NQ + k] = red[k] + red[64 + k] + red[128 + k] + red[192 + k];
}

/* ============================================================
 * Kernel 2: finalize norms (fixed order)
 * ============================================================ */
__global__ void hsq_norm(void)
{
    const int k = threadIdx.x;
    float s = 0.0f;
    for (int e = 0; e < DIM; e++)
        s += g_nsq_part[e * NQ + k];
    g_norm[k] = sqrtf(s);
}

/* ============================================================
 * Kernel 3: GEMM G = P @ W^T via mma.sync bf16x3.
 * CTA 128m x 128n, warps 4m x 2n (warp tile 32x64),
 * K = 8 chunks of 64, cp.async double buffer (2 x 64 KB).
 * ============================================================ */
__global__ __launch_bounds__(256, 1) void hsq_gemm(void)
{
    extern __shared__ char sm[];
    const int t  = threadIdx.x;
    const int l  = t & 31;
    const int w  = t >> 5;
    const int wn = w & 1;            /* n-warp: owns one e (64 cols) */
    const int wm = w >> 1;           /* m-warp 0..3 */
    const int b0 = blockIdx.x * 128;
    const int nt = blockIdx.y;
    const int n0 = nt * 128;
    const uint32_t sbase = s2u(sm);

    /* stage layout: Ah @0 (16K), Al @16K, Bh @32K, Bl @48K; stage stride 64K */
    auto load_chunk = [&](int s, int c) {
        const int d0 = c * 64;
        const uint32_t st = sbase + (uint32_t)s * 65536u;
        #pragma unroll
        for (int u = t; u < 1024; u += 256) {
            const int row = u >> 3, sub = u & 7;
            const uint32_t off = SWZ((uint32_t)(row * 128 + sub * 16));
            const size_t ao = (size_t)(b0 + row) * DIM + d0 + sub * 8;
            cpa16(st + off,          g_Ph + ao);
            cpa16(st + 16384u + off, g_Pl + ao);
            const size_t bo = (size_t)(n0 + row) * DIM + d0 + sub * 8;
            cpa16(st + 32768u + off, g_Wh + bo);
            cpa16(st + 49152u + off, g_Wl + bo);
        }
    };

    load_chunk(0, 0);
    asm volatile("cp.async.commit_group;");

    float C[2][8][4] = {};

    for (int c = 0; c < 8; c++) {
        if (c + 1 < 8) load_chunk((c + 1) & 1, c + 1);
        asm volatile("cp.async.commit_group;");
        asm volatile("cp.async.wait_group 1;");
        __syncthreads();

        const uint32_t st = sbase + (uint32_t)(c & 1) * 65536u;

        #pragma unroll
        for (int kk = 0; kk < 4; kk++) {
            uint32_t ah[2][4], al[2][4];
            #pragma unroll
            for (int mi = 0; mi < 2; mi++) {
                const int row = wm * 32 + mi * 16 + (l & 15);
                const uint32_t kb = (uint32_t)(kk * 32 + ((l >> 4) << 4));
                const uint32_t off = SWZ((uint32_t)(row * 128) + kb);
                ldsm4(ah[mi], st + off);
                ldsm4(al[mi], st + 16384u + off);
            }
            uint32_t bh[8][2], bl[8][2];
            #pragma unroll
            for (int nj = 0; nj < 4; nj++) {
                const int nrow = wn * 64 + nj * 16 + (l & 7) + ((l >> 4) << 3);
                const uint32_t kb = (uint32_t)(kk * 32 + (((l >> 3) & 1) << 4));
                const uint32_t off = SWZ((uint32_t)(nrow * 128) + kb);
                uint32_t r[4];
                ldsm4(r, st + 32768u + off);
                bh[2 * nj][0] = r[0]; bh[2 * nj][1] = r[1];
                bh[2 * nj + 1][0] = r[2]; bh[2 * nj + 1][1] = r[3];
                ldsm4(r, st + 49152u + off);
                bl[2 * nj][0] = r[0]; bl[2 * nj][1] = r[1];
                bl[2 * nj + 1][0] = r[2]; bl[2 * nj + 1][1] = r[3];
            }
            #pragma unroll
            for (int mi = 0; mi < 2; mi++)
                #pragma unroll
                for (int nf = 0; nf < 8; nf++) {
                    mma16816(C[mi][nf], ah[mi], bh[nf]);
                    mma16816(C[mi][nf], ah[mi], bl[nf]);
                    mma16816(C[mi][nf], al[mi], bh[nf]);
                }
        }
        __syncthreads();
    }

    /* epilogue: store to G[e][b][k]; this warp's e is fixed */
    const int e = nt * 2 + wn;
    float* gbase = g_G + ((size_t)e << 17);
    #pragma unroll
    for (int mi = 0; mi < 2; mi++) {
        const int m = b0 + wm * 32 + mi * 16 + (l >> 2);
        #pragma unroll
        for (int nf = 0; nf < 8; nf++) {
            const int k = nf * 8 + 2 * (l & 3);
            *(float2*)(gbase + (size_t)m * 64 + k)       = make_float2(C[mi][nf][0], C[mi][nf][1]);
            *(float2*)(gbase + (size_t)(m + 8) * 64 + k) = make_float2(C[mi][nf][2], C[mi][nf][3]);
        }
    }
}

/* ============================================================
 * Kernel 4: fold + score. CTA: 4 b-rows x 64 k (256 thr).
 * ============================================================ */
__global__ __launch_bounds__(256, 1) void hsq_fold(const float* __restrict__ points,
                                                   const float* __restrict__ l_coefs,
                                                   const float* __restrict__ free_coefs,
                                                   float* __restrict__ out)
{
    extern __shared__ float fs[];
    float* ls  = fs;            /* l_coefs staged: 512 x 64 */
    float* psh = fs + 32768;    /* 4 x 512 p rows */

    const int b0 = blockIdx.x * 4;
    const int t  = threadIdx.x;

    for (int i = t; i < DIM * NQ; i += 256) ls[i] = l_coefs[i];
    for (int i = t; i < 4 * DIM; i += 256)  psh[i] = points[(size_t)b0 * DIM + i];
    __syncthreads();

    const int k  = t & 63;
    const int bi = t >> 6;
    const int b  = b0 + bi;

    float grad = 0.0f, pg = 0.0f;
    const float* gp = g_G + ((size_t)b << 6) + k;
    #pragma unroll 4
    for (int e = 0; e < DIM; e++) {
        const float g  = gp[(size_t)e << 17] + ls[(e << 6) + k];
        const float pe = psh[bi * DIM + e];
        grad = fmaf(g, g, grad);
        pg   = fmaf(pe, g, pg);
    }

    float pl = 0.0f;
    #pragma unroll 8
    for (int d = 0; d < DIM; d++)
        pl = fmaf(psh[bi * DIM + d], ls[(d << 6) + k], pl);

    const float nrm    = g_norm[k];
    const float values = fabsf(0.5f * (pg + pl) + free_coefs[k]);
    const float score  = (sqrtf(grad * 0.25f + values * nrm) - 0.5f * sqrtf(grad)) / nrm;
    out[(size_t)b * NQ + k] = score;
}

/* ============================================================ */
extern "C" void kernel_launch(void* const* d_in, const int* in_sizes, int n_in,
                              void* d_out, int out_size)
{
    const float* points = nullptr;
    const float* q      = nullptr;
    const float* l      = nullptr;
    const float* fr     = nullptr;

    for (int i = 0; i < n_in; i++) {
        switch (in_sizes[i]) {
            case NB * DIM:    points = (const float*)d_in[i]; break;
            case 131328 * NQ: q      = (const float*)d_in[i]; break;
            case DIM * NQ:    l      = (const float*)d_in[i]; break;
            case NQ:          fr     = (const float*)d_in[i]; break;
        }
    }
    if (!points) points = (const float*)d_in[0];
    if (!q)      q      = (const float*)d_in[1];
    if (!l)      l      = (const float*)d_in[2];
    if (!fr)     fr     = (const float*)d_in[3];

    cudaFuncSetAttribute(hsq_gemm, cudaFuncAttributeMaxDynamicSharedMemorySize, 131072);
    cudaFuncSetAttribute(hsq_fold, cudaFuncAttributeMaxDynamicSharedMemorySize, 139264);

    hsq_psplit<<<512, 256>>>(points);
    hsq_prep<<<DIM, 256>>>(q);
    hsq_norm<<<1, 64>>>();

    dim3 ggrid(NB / 128, NTOT / 128);           /* (16, 256); x fastest -> B tile L2 reuse */
    hsq_gemm<<<ggrid, 256, 131072>>>();

    hsq_fold<<<NB / 4, 256, 139264>>>(points, l, fr, (float*)d_out);
}

// round 13
// speedup vs baseline: 3.0615x; 1.2262x over previous
#include <cuda_runtime.h>
#include <cuda_bf16.h>
#include <math.h>
#include <stdint.h>

#define DIM   512
#define NQ    64
#define NB    2048
#define NTOT  32768                 /* N = 512 e * 64 k */
#define SQRT2 1.4142135623730951f

/* ---- scratch (static device globals; no allocation APIs) ---- */
__device__ __nv_bfloat16 g_Wh[(size_t)NTOT * DIM];   /* W hi, [n=(e,k)][d], 32 MB */
__device__ __nv_bfloat16 g_Wl[(size_t)NTOT * DIM];   /* W lo */
__device__ __nv_bfloat16 g_Ph[(size_t)NB * DIM];     /* P hi */
__device__ __nv_bfloat16 g_Pl[(size_t)NB * DIM];     /* P lo */
__device__ float         g_G [(size_t)NB * DIM * NQ];/* G[b][e][k] fp32, 256 MB */
__device__ float         g_nsq_part[DIM * NQ];
__device__ float         g_norm[NQ];

#define SWZ(o) ((o) ^ (((o) >> 3) & 0x70))

__device__ __forceinline__ void cpa16(uint32_t dst, const void* src) {
    asm volatile("cp.async.cg.shared.global [%0], [%1], 16;" :: "r"(dst), "l"(src));
}
__device__ __forceinline__ uint32_t s2u(const void* p) {
    return (uint32_t)__cvta_generic_to_shared(p);
}
__device__ __forceinline__ void ldsm4(uint32_t* r, uint32_t addr) {
    asm volatile("ldmatrix.sync.aligned.m8n8.x4.shared.b16 {%0,%1,%2,%3}, [%4];"
                 : "=r"(r[0]), "=r"(r[1]), "=r"(r[2]), "=r"(r[3]) : "r"(addr));
}
__device__ __forceinline__ void mma16816(float* c, const uint32_t* a, const uint32_t* b) {
    asm volatile(
        "mma.sync.aligned.m16n8k16.row.col.f32.bf16.bf16.f32 "
        "{%0,%1,%2,%3}, {%4,%5,%6,%7}, {%8,%9}, {%0,%1,%2,%3};"
        : "+f"(c[0]), "+f"(c[1]), "+f"(c[2]), "+f"(c[3])
        : "r"(a[0]), "r"(a[1]), "r"(a[2]), "r"(a[3]), "r"(b[0]), "r"(b[1]));
}

/* ============================================================
 * Kernel 0: split P into bf16 hi/lo
 * ============================================================ */
__global__ __launch_bounds__(256) void hsq_psplit(const float* __restrict__ points)
{
    for (int i = blockIdx.x * 256 + threadIdx.x; i < NB * DIM; i += gridDim.x * 256) {
        const float v = points[i];
        const __nv_bfloat16 h = __float2bfloat16(v);
        g_Ph[i] = h;
        g_Pl[i] = __float2bfloat16(v - __bfloat162float(h));
    }
}

/* ============================================================
 * Kernel 1: build W-bf16 [n=(e,k)][d] hi/lo + partial norms
 * ============================================================ */
__global__ __launch_bounds__(256) void hsq_prep(const float* __restrict__ q_coefs)
{
    __shared__ float vs[64][65];
    const int e  = blockIdx.x;
    const int t  = threadIdx.x;
    const int k  = t & 63;
    const int ds = t >> 6;
    float nsq = 0.0f;

    for (int d0 = 0; d0 < DIM; d0 += 64) {
        #pragma unroll 4
        for (int it = 0; it < 16; it++) {
            const int d = d0 + it * 4 + ds;
            const int i = d < e ? d : e;
            const int j = d < e ? e : d;
            const int m = i * DIM - (i * (i - 1)) / 2 + (j - i);
            const float qv = q_coefs[(size_t)m * NQ + k];
            vs[it * 4 + ds][k] = qv * ((d == e) ? 2.0f : SQRT2);
            if (d <= e) nsq += qv * qv;
        }
        __syncthreads();
        const int dl = t & 63;
        const int ks = t >> 6;
        #pragma unroll 4
        for (int kk = 0; kk < 16; kk++) {
            const int kq = kk * 4 + ks;
            const float v = vs[dl][kq];
            const __nv_bfloat16 h = __float2bfloat16(v);
            const size_t o = ((size_t)((e << 6) + kq)) * DIM + d0 + dl;
            g_Wh[o] = h;
            g_Wl[o] = __float2bfloat16(v - __bfloat162float(h));
        }
        __syncthreads();
    }

    __shared__ float red[256];
    red[t] = nsq;
    __syncthreads();
    if (ds == 0)
        g_nsq_part[e * NQ + k] = red[k] + red[64 + k] + red[128 + k] + red[192 + k];
}

/* ============================================================
 * Kernel 2: finalize norms — 64 blocks, deterministic tree
 * ============================================================ */
__global__ __launch_bounds__(256) void hsq_norm(void)
{
    __shared__ float sh[256];
    const int k = blockIdx.x;
    float s = 0.0f;
    for (int e = threadIdx.x; e < DIM; e += 256)
        s += g_nsq_part[e * NQ + k];
    sh[threadIdx.x] = s;
    __syncthreads();
    #pragma unroll
    for (int o = 128; o > 0; o >>= 1) {
        if (threadIdx.x < o) sh[threadIdx.x] += sh[threadIdx.x + o];
        __syncthreads();
    }
    if (threadIdx.x == 0) g_norm[k] = sqrtf(sh[0]);
}

/* ============================================================
 * Kernel 3: GEMM G = P @ W^T via mma.sync bf16x3.
 * CTA 128m x 128n, warps 4m x 2n (warp tile 32x64),
 * K = 8 chunks of 64, 3-stage cp.async pipeline (3 x 64 KB).
 * Output G stored [b][e][k].
 * ============================================================ */
__global__ __launch_bounds__(256, 1) void hsq_gemm(void)
{
    extern __shared__ char sm[];
    const int t  = threadIdx.x;
    const int l  = t & 31;
    const int w  = t >> 5;
    const int wn = w & 1;            /* n-warp: owns one e (64 cols) */
    const int wm = w >> 1;           /* m-warp 0..3 */
    const int b0 = blockIdx.x * 128;
    const int nt = blockIdx.y;
    const int n0 = nt * 128;
    const uint32_t sbase = s2u(sm);

    /* stage layout: Ah @0 (16K), Al @16K, Bh @32K, Bl @48K; stage stride 64K */
    auto load_chunk = [&](int s, int c) {
        const int d0 = c * 64;
        const uint32_t st = sbase + (uint32_t)s * 65536u;
        #pragma unroll
        for (int u = t; u < 1024; u += 256) {
            const int row = u >> 3, sub = u & 7;
            const uint32_t off = SWZ((uint32_t)(row * 128 + sub * 16));
            const size_t ao = (size_t)(b0 + row) * DIM + d0 + sub * 8;
            cpa16(st + off,          g_Ph + ao);
            cpa16(st + 16384u + off, g_Pl + ao);
            const size_t bo = (size_t)(n0 + row) * DIM + d0 + sub * 8;
            cpa16(st + 32768u + off, g_Wh + bo);
            cpa16(st + 49152u + off, g_Wl + bo);
        }
    };

    load_chunk(0, 0);
    asm volatile("cp.async.commit_group;");
    load_chunk(1, 1);
    asm volatile("cp.async.commit_group;");

    float C[2][8][4] = {};

    for (int c = 0; c < 8; c++) {
        if (c + 2 < 8) load_chunk((c + 2) % 3, c + 2);
        asm volatile("cp.async.commit_group;");
        asm volatile("cp.async.wait_group 2;");
        __syncthreads();

        const uint32_t st = sbase + (uint32_t)(c % 3) * 65536u;

        #pragma unroll
        for (int kk = 0; kk < 4; kk++) {
            uint32_t ah[2][4], al[2][4];
            #pragma unroll
            for (int mi = 0; mi < 2; mi++) {
                const int row = wm * 32 + mi * 16 + (l & 15);
                const uint32_t kb = (uint32_t)(kk * 32 + ((l >> 4) << 4));
                const uint32_t off = SWZ((uint32_t)(row * 128) + kb);
                ldsm4(ah[mi], st + off);
                ldsm4(al[mi], st + 16384u + off);
            }
            uint32_t bh[8][2], bl[8][2];
            #pragma unroll
            for (int nj = 0; nj < 4; nj++) {
                const int nrow = wn * 64 + nj * 16 + (l & 7) + ((l >> 4) << 3);
                const uint32_t kb = (uint32_t)(kk * 32 + (((l >> 3) & 1) << 4));
                const uint32_t off = SWZ((uint32_t)(nrow * 128) + kb);
                uint32_t r[4];
                ldsm4(r, st + 32768u + off);
                bh[2 * nj][0] = r[0]; bh[2 * nj][1] = r[1];
                bh[2 * nj + 1][0] = r[2]; bh[2 * nj + 1][1] = r[3];
                ldsm4(r, st + 49152u + off);
                bl[2 * nj][0] = r[0]; bl[2 * nj][1] = r[1];
                bl[2 * nj + 1][0] = r[2]; bl[2 * nj + 1][1] = r[3];
            }
            #pragma unroll
            for (int mi = 0; mi < 2; mi++)
                #pragma unroll
                for (int nf = 0; nf < 8; nf++) {
                    mma16816(C[mi][nf], ah[mi], bh[nf]);
                    mma16816(C[mi][nf], ah[mi], bl[nf]);
                    mma16816(C[mi][nf], al[mi], bh[nf]);
                }
        }
        __syncthreads();
    }

    /* epilogue: store to G[b][e][k]; this warp's e is fixed */
    const int e = nt * 2 + wn;
    #pragma unroll
    for (int mi = 0; mi < 2; mi++) {
        const int m = b0 + wm * 32 + mi * 16 + (l >> 2);
        #pragma unroll
        for (int nf = 0; nf < 8; nf++) {
            const int k = nf * 8 + 2 * (l & 3);
            *(float2*)(g_G + (size_t)m * (DIM * NQ) + e * NQ + k) =
                make_float2(C[mi][nf][0], C[mi][nf][1]);
            *(float2*)(g_G + (size_t)(m + 8) * (DIM * NQ) + e * NQ + k) =
                make_float2(C[mi][nf][2], C[mi][nf][3]);
        }
    }
}

/* ============================================================
 * Kernel 4: fold + score. CTA: 4 b-rows x 64 k (256 thr).
 * G[b][e][k] now contiguous along (e,k) per b — streaming reads.
 * ============================================================ */
__global__ __launch_bounds__(256, 1) void hsq_fold(const float* __restrict__ points,
                                                   const float* __restrict__ l_coefs,
                                                   const float* __restrict__ free_coefs,
                                                   float* __restrict__ out)
{
    extern __shared__ float fs[];
    float* ls  = fs;            /* l_coefs staged: 512 x 64 */
    float* psh = fs + 32768;    /* 4 x 512 p rows */

    const int b0 = blockIdx.x * 4;
    const int t  = threadIdx.x;

    for (int i = t; i < DIM * NQ; i += 256) ls[i] = l_coefs[i];
    for (int i = t; i < 4 * DIM; i += 256)  psh[i] = points[(size_t)b0 * DIM + i];
    __syncthreads();

    const int k  = t & 63;
    const int bi = t >> 6;
    const int b  = b0 + bi;

    float grad = 0.0f, pg = 0.0f;
    const float* gp = g_G + (size_t)b * (DIM * NQ) + k;
    #pragma unroll 8
    for (int e = 0; e < DIM; e++) {
        const float g  = gp[e << 6] + ls[(e << 6) + k];
        const float pe = psh[bi * DIM + e];
        grad = fmaf(g, g, grad);
        pg   = fmaf(pe, g, pg);
    }

    float pl = 0.0f;
    #pragma unroll 8
    for (int d = 0; d < DIM; d++)
        pl = fmaf(psh[bi * DIM + d], ls[(d << 6) + k], pl);

    const float nrm    = g_norm[k];
    const float values = fabsf(0.5f * (pg + pl) + free_coefs[k]);
    const float score  = (sqrtf(grad * 0.25f + values * nrm) - 0.5f * sqrtf(grad)) / nrm;
    out[(size_t)b * NQ + k] = score;
}

/* ============================================================ */
extern "C" void kernel_launch(void* const* d_in, const int* in_sizes, int n_in,
                              void* d_out, int out_size)
{
    const float* points = nullptr;
    const float* q      = nullptr;
    const float* l      = nullptr;
    const float* fr     = nullptr;

    for (int i = 0; i < n_in; i++) {
        switch (in_sizes[i]) {
            case NB * DIM:    points = (const float*)d_in[i]; break;
            case 131328 * NQ: q      = (const float*)d_in[i]; break;
            case DIM * NQ:    l      = (const float*)d_in[i]; break;
            case NQ:          fr     = (const float*)d_in[i]; break;
        }
    }
    if (!points) points = (const float*)d_in[0];
    if (!q)      q      = (const float*)d_in[1];
    if (!l)      l      = (const float*)d_in[2];
    if (!fr)     fr     = (const float*)d_in[3];

    cudaFuncSetAttribute(hsq_gemm, cudaFuncAttributeMaxDynamicSharedMemorySize, 196608);
    cudaFuncSetAttribute(hsq_fold, cudaFuncAttributeMaxDynamicSharedMemorySize, 139264);

    hsq_psplit<<<512, 256>>>(points);
    hsq_prep<<<DIM, 256>>>(q);
    hsq_norm<<<64, 256>>>();

    dim3 ggrid(NB / 128, NTOT / 128);           /* (16, 256); x fastest -> B tile L2 reuse */
    hsq_gemm<<<ggrid, 256, 196608>>>();

    hsq_fold<<<NB / 4, 256, 139264>>>(points, l, fr, (float*)d_out);
}

// round 14
// speedup vs baseline: 4.9147x; 1.6053x over previous
#include <cuda_runtime.h>
#include <cuda_fp16.h>
#include <math.h>
#include <stdint.h>

#define DIM   512
#define NQ    64
#define NB    2048
#define NTOT  32768                 /* N = 512 e * 64 k */
#define SQRT2 1.4142135623730951f

/* ---- scratch (static device globals; no allocation APIs) ---- */
__device__ __half g_Wh[(size_t)NTOT * DIM];           /* W fp16, [n=(e,k)][d], 32 MB */
__device__ __half g_Ph[(size_t)NB * DIM];             /* P fp16 */
__device__ float  g_G [(size_t)NB * DIM * NQ];        /* G[b][e][k] fp32, 256 MB */
__device__ float  g_nsq_part[DIM * NQ];
__device__ float  g_norm[NQ];

#define SWZ(o) ((o) ^ (((o) >> 3) & 0x70))

__device__ __forceinline__ void cpa16(uint32_t dst, const void* src) {
    asm volatile("cp.async.cg.shared.global [%0], [%1], 16;" :: "r"(dst), "l"(src));
}
__device__ __forceinline__ uint32_t s2u(const void* p) {
    return (uint32_t)__cvta_generic_to_shared(p);
}
__device__ __forceinline__ void ldsm4(uint32_t* r, uint32_t addr) {
    asm volatile("ldmatrix.sync.aligned.m8n8.x4.shared.b16 {%0,%1,%2,%3}, [%4];"
                 : "=r"(r[0]), "=r"(r[1]), "=r"(r[2]), "=r"(r[3]) : "r"(addr));
}
__device__ __forceinline__ void mma16816(float* c, const uint32_t* a, const uint32_t* b) {
    asm volatile(
        "mma.sync.aligned.m16n8k16.row.col.f32.f16.f16.f32 "
        "{%0,%1,%2,%3}, {%4,%5,%6,%7}, {%8,%9}, {%0,%1,%2,%3};"
        : "+f"(c[0]), "+f"(c[1]), "+f"(c[2]), "+f"(c[3])
        : "r"(a[0]), "r"(a[1]), "r"(a[2]), "r"(a[3]), "r"(b[0]), "r"(b[1]));
}

/* ============================================================
 * Kernel 0: convert P to fp16
 * ============================================================ */
__global__ __launch_bounds__(256) void hsq_psplit(const float* __restrict__ points)
{
    for (int i = blockIdx.x * 256 + threadIdx.x; i < NB * DIM; i += gridDim.x * 256)
        g_Ph[i] = __float2half(points[i]);
}

/* ============================================================
 * Kernel 1: build W-fp16 [n=(e,k)][d] + partial norms. 1 blk/e.
 * ============================================================ */
__global__ __launch_bounds__(256) void hsq_prep(const float* __restrict__ q_coefs)
{
    __shared__ float vs[64][65];
    const int e  = blockIdx.x;
    const int t  = threadIdx.x;
    const int k  = t & 63;
    const int ds = t >> 6;
    float nsq = 0.0f;

    for (int d0 = 0; d0 < DIM; d0 += 64) {
        #pragma unroll 4
        for (int it = 0; it < 16; it++) {
            const int d = d0 + it * 4 + ds;
            const int i = d < e ? d : e;
            const int j = d < e ? e : d;
            const int m = i * DIM - (i * (i - 1)) / 2 + (j - i);
            const float qv = q_coefs[(size_t)m * NQ + k];
            vs[it * 4 + ds][k] = qv * ((d == e) ? 2.0f : SQRT2);
            if (d <= e) nsq += qv * qv;
        }
        __syncthreads();
        const int dl = t & 63;
        const int ks = t >> 6;
        #pragma unroll 4
        for (int kk = 0; kk < 16; kk++) {
            const int kq = kk * 4 + ks;
            g_Wh[((size_t)((e << 6) + kq)) * DIM + d0 + dl] = __float2half(vs[dl][kq]);
        }
        __syncthreads();
    }

    __shared__ float red[256];
    red[t] = nsq;
    __syncthreads();
    if (ds == 0)
        g_nsq_part[e * NQ + k] = red[k] + red[64 + k] + red[128 + k] + red[192 + k];
}

/* ============================================================
 * Kernel 2: finalize norms — 64 blocks, deterministic tree
 * ============================================================ */
__global__ __launch_bounds__(256) void hsq_norm(void)
{
    __shared__ float sh[256];
    const int k = blockIdx.x;
    float s = 0.0f;
    for (int e = threadIdx.x; e < DIM; e += 256)
        s += g_nsq_part[e * NQ + k];
    sh[threadIdx.x] = s;
    __syncthreads();
    #pragma unroll
    for (int o = 128; o > 0; o >>= 1) {
        if (threadIdx.x < o) sh[threadIdx.x] += sh[threadIdx.x + o];
        __syncthreads();
    }
    if (threadIdx.x == 0) g_norm[k] = sqrtf(sh[0]);
}

/* ============================================================
 * Kernel 3: GEMM G = P @ W^T via mma.sync fp16 (single pass).
 * CTA 128m x 256n, 512 thr, warps 4m x 4n (warp tile 32x64),
 * K = 8 chunks of 64, 4-stage cp.async pipeline (4 x 48 KB).
 * Output G stored [b][e][k].
 * ============================================================ */
__global__ __launch_bounds__(512, 1) void hsq_gemm(void)
{
    extern __shared__ char sm[];
    const int t  = threadIdx.x;
    const int l  = t & 31;
    const int w  = t >> 5;
    const int wn = w & 3;            /* n-warp: owns one e (64 cols) */
    const int wm = w >> 2;           /* m-warp 0..3 */
    const int b0 = blockIdx.x * 128;
    const int nt = blockIdx.y;
    const int n0 = nt * 256;
    const uint32_t sbase = s2u(sm);

    /* stage: A @0 (16 KB = 128 rows x 128 B), B @16K (32 KB = 256 rows); stride 48 KB */
    auto load_chunk = [&](int s, int c) {
        const int d0 = c * 64;
        const uint32_t st = sbase + (uint32_t)s * 49152u;
        #pragma unroll
        for (int u = t; u < 1024; u += 512) {
            const int row = u >> 3, sub = u & 7;
            const uint32_t off = SWZ((uint32_t)(row * 128 + sub * 16));
            cpa16(st + off, g_Ph + (size_t)(b0 + row) * DIM + d0 + sub * 8);
        }
        #pragma unroll
        for (int u = t; u < 2048; u += 512) {
            const int row = u >> 3, sub = u & 7;
            const uint32_t off = SWZ((uint32_t)(row * 128 + sub * 16));
            cpa16(st + 16384u + off, g_Wh + (size_t)(n0 + row) * DIM + d0 + sub * 8);
        }
    };

    load_chunk(0, 0);
    asm volatile("cp.async.commit_group;");
    load_chunk(1, 1);
    asm volatile("cp.async.commit_group;");
    load_chunk(2, 2);
    asm volatile("cp.async.commit_group;");

    float C[2][8][4] = {};

    for (int c = 0; c < 8; c++) {
        if (c + 3 < 8) load_chunk((c + 3) & 3, c + 3);
        asm volatile("cp.async.commit_group;");
        asm volatile("cp.async.wait_group 3;");
        __syncthreads();

        const uint32_t st = sbase + (uint32_t)(c & 3) * 49152u;

        #pragma unroll
        for (int kk = 0; kk < 4; kk++) {
            uint32_t ah[2][4];
            #pragma unroll
            for (int mi = 0; mi < 2; mi++) {
                const int row = wm * 32 + mi * 16 + (l & 15);
                const uint32_t kb = (uint32_t)(kk * 32 + ((l >> 4) << 4));
                ldsm4(ah[mi], st + SWZ((uint32_t)(row * 128) + kb));
            }
            uint32_t bh[8][2];
            #pragma unroll
            for (int nj = 0; nj < 4; nj++) {
                const int nrow = wn * 64 + nj * 16 + (l & 7) + ((l >> 4) << 3);
                const uint32_t kb = (uint32_t)(kk * 32 + (((l >> 3) & 1) << 4));
                uint32_t r[4];
                ldsm4(r, st + 16384u + SWZ((uint32_t)(nrow * 128) + kb));
                bh[2 * nj][0] = r[0]; bh[2 * nj][1] = r[1];
                bh[2 * nj + 1][0] = r[2]; bh[2 * nj + 1][1] = r[3];
            }
            #pragma unroll
            for (int mi = 0; mi < 2; mi++)
                #pragma unroll
                for (int nf = 0; nf < 8; nf++)
                    mma16816(C[mi][nf], ah[mi], bh[nf]);
        }
        __syncthreads();
    }

    /* epilogue: store to G[b][e][k]; this warp's e is fixed */
    const int e = nt * 4 + wn;
    #pragma unroll
    for (int mi = 0; mi < 2; mi++) {
        const int m = b0 + wm * 32 + mi * 16 + (l >> 2);
        #pragma unroll
        for (int nf = 0; nf < 8; nf++) {
            const int k = nf * 8 + 2 * (l & 3);
            *(float2*)(g_G + (size_t)m * (DIM * NQ) + e * NQ + k) =
                make_float2(C[mi][nf][0], C[mi][nf][1]);
            *(float2*)(g_G + (size_t)(m + 8) * (DIM * NQ) + e * NQ + k) =
                make_float2(C[mi][nf][2], C[mi][nf][3]);
        }
    }
}

/* ============================================================
 * Kernel 4: fold + score. CTA: 4 b-rows x 64 k (256 thr).
 * G[b][e][k] contiguous along (e,k) per b — streaming reads.
 * ============================================================ */
__global__ __launch_bounds__(256, 1) void hsq_fold(const float* __restrict__ points,
                                                   const float* __restrict__ l_coefs,
                                                   const float* __restrict__ free_coefs,
                                                   float* __restrict__ out)
{
    extern __shared__ float fs[];
    float* ls  = fs;            /* l_coefs staged: 512 x 64 */
    float* psh = fs + 32768;    /* 4 x 512 p rows */

    const int b0 = blockIdx.x * 4;
    const int t  = threadIdx.x;

    for (int i = t; i < DIM * NQ; i += 256) ls[i] = l_coefs[i];
    for (int i = t; i < 4 * DIM; i += 256)  psh[i] = points[(size_t)b0 * DIM + i];
    __syncthreads();

    const int k  = t & 63;
    const int bi = t >> 6;
    const int b  = b0 + bi;

    float grad = 0.0f, pg = 0.0f;
    const float* gp = g_G + (size_t)b * (DIM * NQ) + k;
    #pragma unroll 8
    for (int e = 0; e < DIM; e++) {
        const float g  = gp[e << 6] + ls[(e << 6) + k];
        const float pe = psh[bi * DIM + e];
        grad = fmaf(g, g, grad);
        pg   = fmaf(pe, g, pg);
    }

    float pl = 0.0f;
    #pragma unroll 8
    for (int d = 0; d < DIM; d++)
        pl = fmaf(psh[bi * DIM + d], ls[(d << 6) + k], pl);

    const float nrm    = g_norm[k];
    const float values = fabsf(0.5f * (pg + pl) + free_coefs[k]);
    const float score  = (sqrtf(grad * 0.25f + values * nrm) - 0.5f * sqrtf(grad)) / nrm;
    out[(size_t)b * NQ + k] = score;
}

/* ============================================================ */
extern "C" void kernel_launch(void* const* d_in, const int* in_sizes, int n_in,
                              void* d_out, int out_size)
{
    const float* points = nullptr;
    const float* q      = nullptr;
    const float* l      = nullptr;
    const float* fr     = nullptr;

    for (int i = 0; i < n_in; i++) {
        switch (in_sizes[i]) {
            case NB * DIM:    points = (const float*)d_in[i]; break;
            case 131328 * NQ: q      = (const float*)d_in[i]; break;
            case DIM * NQ:    l      = (const float*)d_in[i]; break;
            case NQ:          fr     = (const float*)d_in[i]; break;
        }
    }
    if (!points) points = (const float*)d_in[0];
    if (!q)      q      = (const float*)d_in[1];
    if (!l)      l      = (const float*)d_in[2];
    if (!fr)     fr     = (const float*)d_in[3];

    cudaFuncSetAttribute(hsq_gemm, cudaFuncAttributeMaxDynamicSharedMemorySize, 196608);
    cudaFuncSetAttribute(hsq_fold, cudaFuncAttributeMaxDynamicSharedMemorySize, 139264);

    hsq_psplit<<<512, 256>>>(points);
    hsq_prep<<<DIM, 256>>>(q);
    hsq_norm<<<64, 256>>>();

    dim3 ggrid(NB / 128, NTOT / 256);           /* (16, 128); x fastest -> B tile L2 reuse */
    hsq_gemm<<<ggrid, 512, 196608>>>();

    hsq_fold<<<NB / 4, 256, 139264>>>(points, l, fr, (float*)d_out);
}

// round 16
// speedup vs baseline: 4.9225x; 1.0016x over previous
#include <cuda_runtime.h>
#include <cuda_fp16.h>
#include <math.h>
#include <stdint.h>

#define DIM   512
#define NQ    64
#define NB    2048
#define NTOT  32768                 /* N = 512 e * 64 k */
#define NTIL  128                   /* n-tiles (256 n each) */
#define SQRT2 1.4142135623730951f

/* ---- scratch (static device globals; no allocation APIs) ---- */
__device__ __half g_Wh[(size_t)NTOT * DIM];           /* W fp16, [n=(e,k)][d], 32 MB */
__device__ __half g_Ph[(size_t)NB * DIM];             /* P fp16 */
__device__ float  g_pgr[(size_t)NB * NTIL * NQ];      /* grad partials [b][nt][k], 67 MB */
__device__ float  g_ppg[(size_t)NB * NTIL * NQ];      /* pg partials   [b][nt][k], 67 MB */
__device__ float  g_nsq_part[DIM * NQ];
__device__ float  g_norm[NQ];

#define SWZ(o) ((o) ^ (((o) >> 3) & 0x70))

__device__ __forceinline__ void cpa16(uint32_t dst, const void* src) {
    asm volatile("cp.async.cg.shared.global [%0], [%1], 16;" :: "r"(dst), "l"(src));
}
__device__ __forceinline__ uint32_t s2u(const void* p) {
    return (uint32_t)__cvta_generic_to_shared(p);
}
__device__ __forceinline__ void ldsm4(uint32_t* r, uint32_t addr) {
    asm volatile("ldmatrix.sync.aligned.m8n8.x4.shared.b16 {%0,%1,%2,%3}, [%4];"
                 : "=r"(r[0]), "=r"(r[1]), "=r"(r[2]), "=r"(r[3]) : "r"(addr));
}
__device__ __forceinline__ void mma16816(float* c, const uint32_t* a, const uint32_t* b) {
    asm volatile(
        "mma.sync.aligned.m16n8k16.row.col.f32.f16.f16.f32 "
        "{%0,%1,%2,%3}, {%4,%5,%6,%7}, {%8,%9}, {%0,%1,%2,%3};"
        : "+f"(c[0]), "+f"(c[1]), "+f"(c[2]), "+f"(c[3])
        : "r"(a[0]), "r"(a[1]), "r"(a[2]), "r"(a[3]), "r"(b[0]), "r"(b[1]));
}

/* ============================================================
 * Kernel 0: convert P to fp16
 * ============================================================ */
__global__ __launch_bounds__(256) void hsq_psplit(const float* __restrict__ points)
{
    for (int i = blockIdx.x * 256 + threadIdx.x; i < NB * DIM; i += gridDim.x * 256)
        g_Ph[i] = __float2half(points[i]);
}

/* ============================================================
 * Kernel 1: build W-fp16 [n=(e,k)][d] + partial norms. 1 blk/e.
 * ============================================================ */
__global__ __launch_bounds__(256) void hsq_prep(const float* __restrict__ q_coefs)
{
    __shared__ float vs[64][65];
    const int e  = blockIdx.x;
    const int t  = threadIdx.x;
    const int k  = t & 63;
    const int ds = t >> 6;
    float nsq = 0.0f;

    for (int d0 = 0; d0 < DIM; d0 += 64) {
        #pragma unroll 4
        for (int it = 0; it < 16; it++) {
            const int d = d0 + it * 4 + ds;
            const int i = d < e ? d : e;
            const int j = d < e ? e : d;
            const int m = i * DIM - (i * (i - 1)) / 2 + (j - i);
            const float qv = q_coefs[(size_t)m * NQ + k];
            vs[it * 4 + ds][k] = qv * ((d == e) ? 2.0f : SQRT2);
            if (d <= e) nsq += qv * qv;
        }
        __syncthreads();
        const int dl = t & 63;
        const int ks = t >> 6;
        #pragma unroll 4
        for (int kk = 0; kk < 16; kk++) {
            const int kq = kk * 4 + ks;
            g_Wh[((size_t)((e << 6) + kq)) * DIM + d0 + dl] = __float2half(vs[dl][kq]);
        }
        __syncthreads();
    }

    __shared__ float red[256];
    red[t] = nsq;
    __syncthreads();
    if (ds == 0)
        g_nsq_part[e * NQ + k] = red[k] + red[64 + k] + red[128 + k] + red[192 + k];
}

/* ============================================================
 * Kernel 2: finalize norms — 64 blocks, deterministic tree
 * ============================================================ */
__global__ __launch_bounds__(256) void hsq_norm(void)
{
    __shared__ float sh[256];
    const int k = blockIdx.x;
    float s = 0.0f;
    for (int e = threadIdx.x; e < DIM; e += 256)
        s += g_nsq_part[e * NQ + k];
    sh[threadIdx.x] = s;
    __syncthreads();
    #pragma unroll
    for (int o = 128; o > 0; o >>= 1) {
        if (threadIdx.x < o) sh[threadIdx.x] += sh[threadIdx.x + o];
        __syncthreads();
    }
    if (threadIdx.x == 0) g_norm[k] = sqrtf(sh[0]);
}

/* ============================================================
 * Kernel 3: GEMM + fused fold epilogue.
 * CTA 128m x 256n (4 e), 512 thr, warps 4m x 4n (tile 32x64),
 * K = 8 chunks of 64, 4-stage cp.async pipeline (4 x 48 KB).
 * Epilogue: g = C + l[e,k]; accumulate g^2 and p[b,e]*g over the
 * CTA's 4 e in smem (reusing stage buffers), write partials
 * [b][nt][k]. Deterministic: fixed wn pass order.
 * ============================================================ */
__global__ __launch_bounds__(512, 1) void hsq_gemm(const float* __restrict__ points,
                                                   const float* __restrict__ l_coefs)
{
    extern __shared__ char sm[];
    const int t  = threadIdx.x;
    const int l  = t & 31;
    const int w  = t >> 5;
    const int wn = w & 3;            /* n-warp: owns one e (64 cols) */
    const int wm = w >> 2;           /* m-warp 0..3 */
    const int b0 = blockIdx.x * 128;
    const int nt = blockIdx.y;
    const int n0 = nt * 256;
    const uint32_t sbase = s2u(sm);

    /* stage: A @0 (16 KB), B @16K (32 KB); stride 48 KB */
    auto load_chunk = [&](int s, int c) {
        const int d0 = c * 64;
        const uint32_t st = sbase + (uint32_t)s * 49152u;
        #pragma unroll
        for (int u = t; u < 1024; u += 512) {
            const int row = u >> 3, sub = u & 7;
            const uint32_t off = SWZ((uint32_t)(row * 128 + sub * 16));
            cpa16(st + off, g_Ph + (size_t)(b0 + row) * DIM + d0 + sub * 8);
        }
        #pragma unroll
        for (int u = t; u < 2048; u += 512) {
            const int row = u >> 3, sub = u & 7;
            const uint32_t off = SWZ((uint32_t)(row * 128 + sub * 16));
            cpa16(st + 16384u + off, g_Wh + (size_t)(n0 + row) * DIM + d0 + sub * 8);
        }
    };

    load_chunk(0, 0);
    asm volatile("cp.async.commit_group;");
    load_chunk(1, 1);
    asm volatile("cp.async.commit_group;");
    load_chunk(2, 2);
    asm volatile("cp.async.commit_group;");

    float C[2][8][4] = {};

    for (int c = 0; c < 8; c++) {
        if (c + 3 < 8) load_chunk((c + 3) & 3, c + 3);
        asm volatile("cp.async.commit_group;");
        asm volatile("cp.async.wait_group 3;");
        __syncthreads();

        const uint32_t st = sbase + (uint32_t)(c & 3) * 49152u;

        #pragma unroll
        for (int kk = 0; kk < 4; kk++) {
            uint32_t ah[2][4];
            #pragma unroll
            for (int mi = 0; mi < 2; mi++) {
                const int row = wm * 32 + mi * 16 + (l & 15);
                const uint32_t kb = (uint32_t)(kk * 32 + ((l >> 4) << 4));
                ldsm4(ah[mi], st + SWZ((uint32_t)(row * 128) + kb));
            }
            uint32_t bh[8][2];
            #pragma unroll
            for (int nj = 0; nj < 4; nj++) {
                const int nrow = wn * 64 + nj * 16 + (l & 7) + ((l >> 4) << 3);
                const uint32_t kb = (uint32_t)(kk * 32 + (((l >> 3) & 1) << 4));
                uint32_t r[4];
                ldsm4(r, st + 16384u + SWZ((uint32_t)(nrow * 128) + kb));
                bh[2 * nj][0] = r[0]; bh[2 * nj][1] = r[1];
                bh[2 * nj + 1][0] = r[2]; bh[2 * nj + 1][1] = r[3];
            }
            #pragma unroll
            for (int mi = 0; mi < 2; mi++)
                #pragma unroll
                for (int nf = 0; nf < 8; nf++)
                    mma16816(C[mi][nf], ah[mi], bh[nf]);
        }
        __syncthreads();
    }

    /* ---- fused fold epilogue ---- */
    asm volatile("cp.async.wait_group 0;");
    __syncthreads();

    float* grs = (float*)sm;               /* [128 m][64 k] */
    float* pgs = (float*)(sm + 49152);     /* [128 m][64 k] */
    for (int i = t; i < 8192; i += 512) { grs[i] = 0.0f; pgs[i] = 0.0f; }
    __syncthreads();

    const int e  = nt * 4 + wn;
    const int kbase = 2 * (l & 3);
    float lv[8][2];
    #pragma unroll
    for (int nf = 0; nf < 8; nf++) {
        lv[nf][0] = l_coefs[e * NQ + nf * 8 + kbase];
        lv[nf][1] = l_coefs[e * NQ + nf * 8 + kbase + 1];
    }
    float pv[2][2];
    #pragma unroll
    for (int mi = 0; mi < 2; mi++) {
        const int m = b0 + wm * 32 + mi * 16 + (l >> 2);
        pv[mi][0] = points[(size_t)m * DIM + e];
        pv[mi][1] = points[(size_t)(m + 8) * DIM + e];
    }

    #pragma unroll
    for (int pass = 0; pass < 4; pass++) {
        if (wn == pass) {
            #pragma unroll
            for (int mi = 0; mi < 2; mi++) {
                const int m0 = wm * 32 + mi * 16 + (l >> 2);
                #pragma unroll
                for (int nf = 0; nf < 8; nf++) {
                    const int k = nf * 8 + kbase;
                    {
                        const float g0 = C[mi][nf][0] + lv[nf][0];
                        const float g1 = C[mi][nf][1] + lv[nf][1];
                        grs[m0 * 64 + k]     += g0 * g0;
                        grs[m0 * 64 + k + 1] += g1 * g1;
                        pgs[m0 * 64 + k]     += pv[mi][0] * g0;
                        pgs[m0 * 64 + k + 1] += pv[mi][0] * g1;
                    }
                    {
                        const float g0 = C[mi][nf][2] + lv[nf][0];
                        const float g1 = C[mi][nf][3] + lv[nf][1];
                        grs[(m0 + 8) * 64 + k]     += g0 * g0;
                        grs[(m0 + 8) * 64 + k + 1] += g1 * g1;
                        pgs[(m0 + 8) * 64 + k]     += pv[mi][1] * g0;
                        pgs[(m0 + 8) * 64 + k + 1] += pv[mi][1] * g1;
                    }
                }
            }
        }
        __syncthreads();
    }

    /* write partials: [b][nt][k], coalesced float4 */
    for (int i = t; i < 2048; i += 512) {
        const int m  = i >> 4;
        const int k4 = (i & 15) * 4;
        const size_t o = (size_t)(b0 + m) * (NTIL * NQ) + nt * NQ + k4;
        *(float4*)(g_pgr + o) = *(const float4*)(grs + m * 64 + k4);
        *(float4*)(g_ppg + o) = *(const float4*)(pgs + m * 64 + k4);
    }
}

/* ============================================================
 * Kernel 4: reduce partials (fixed nt order) + p.l dot + score.
 * CTA: 4 b-rows x 64 k (256 thr).
 * ============================================================ */
__global__ __launch_bounds__(256, 1) void hsq_fold(const float* __restrict__ points,
                                                   const float* __restrict__ l_coefs,
                                                   const float* __restrict__ free_coefs,
                                                   float* __restrict__ out)
{
    extern __shared__ float fs[];
    float* ls  = fs;            /* l_coefs staged: 512 x 64 */
    float* psh = fs + 32768;    /* 4 x 512 p rows */

    const int b0 = blockIdx.x * 4;
    const int t  = threadIdx.x;

    for (int i = t; i < DIM * NQ; i += 256) ls[i] = l_coefs[i];
    for (int i = t; i < 4 * DIM; i += 256)  psh[i] = points[(size_t)b0 * DIM + i];
    __syncthreads();

    const int k  = t & 63;
    const int bi = t >> 6;
    const int b  = b0 + bi;

    float grad = 0.0f, pg = 0.0f;
    const float* gr = g_pgr + (size_t)b * (NTIL * NQ) + k;
    const float* pp = g_ppg + (size_t)b * (NTIL * NQ) + k;
    #pragma unroll 8
    for (int nt = 0; nt < NTIL; nt++) {
        grad += gr[nt << 6];
        pg   += pp[nt << 6];
    }

    float pl = 0.0f;
    #pragma unroll 8
    for (int d = 0; d < DIM; d++)
        pl = fmaf(psh[bi * DIM + d], ls[(d << 6) + k], pl);

    const float nrm    = g_norm[k];
    const float values = fabsf(0.5f * (pg + pl) + free_coefs[k]);
    const float score  = (sqrtf(grad * 0.25f + values * nrm) - 0.5f * sqrtf(grad)) / nrm;
    out[(size_t)b * NQ + k] = score;
}

/* ============================================================ */
extern "C" void kernel_launch(void* const* d_in, const int* in_sizes, int n_in,
                              void* d_out, int out_size)
{
    const float* points = nullptr;
    const float* q      = nullptr;
    const float* l      = nullptr;
    const float* fr     = nullptr;

    for (int i = 0; i < n_in; i++) {
        switch (in_sizes[i]) {
            case NB * DIM:    points = (const float*)d_in[i]; break;
            case 131328 * NQ: q      = (const float*)d_in[i]; break;
            case DIM * NQ:    l      = (const float*)d_in[i]; break;
            case NQ:          fr     = (const float*)d_in[i]; break;
        }
    }
    if (!points) points = (const float*)d_in[0];
    if (!q)      q      = (const float*)d_in[1];
    if (!l)      l      = (const float*)d_in[2];
    if (!fr)     fr     = (const float*)d_in[3];

    cudaFuncSetAttribute(hsq_gemm, cudaFuncAttributeMaxDynamicSharedMemorySize, 196608);
    cudaFuncSetAttribute(hsq_fold, cudaFuncAttributeMaxDynamicSharedMemorySize, 139264);

    hsq_psplit<<<512, 256>>>(points);
    hsq_prep<<<DIM, 256>>>(q);
    hsq_norm<<<64, 256>>>();

    dim3 ggrid(NB / 128, NTOT / 256);           /* (16, 128); x fastest -> B tile L2 reuse */
    hsq_gemm<<<ggrid, 512, 196608>>>(points, l);

    hsq_fold<<<NB / 4, 256, 139264>>>(points, l, fr, (float*)d_out);
}